// round 7
// baseline (speedup 1.0000x reference)
#include <cuda_runtime.h>
#include <cstdint>

#define NB 4
#define NC 128
#define NH 192
#define NW 192
#define ND 21
#define ND2 441
#define HR 158
#define WRP 160
#define HO 156
#define WO 156

#define APAD_W 164     // floats per A row (41 quads, odd)
#define BPAD_H 200
#define BPAD_W 212     // floats per B row (53 quads, odd)

// smem layout (bytes), 4 stages
#define NSTAGE 4
#define A_ROW 656            // 164 floats
#define A_CC  (8 * A_ROW)    // 5248
#define A_STAGE (4 * A_CC)   // 20992
#define B_ROW 848            // 212 floats
#define B_CC  (8 * B_ROW)    // 6784
#define B_STAGE (4 * B_CC)   // 27136
#define A_OFF 128
#define B_OFF (A_OFF + NSTAGE * A_STAGE)        // 84096
#define SMEM_BYTES (B_OFF + NSTAGE * B_STAGE)   // 192640
#define STAGE_TX (A_STAGE + B_STAGE)            // 48128

// mbarriers: full[s] at sbase + s*8 ; empty[s] at sbase + 32 + s*8

__device__ __align__(16) float g_Apad[(size_t)NB * 20 * NC * 8 * APAD_W];
__device__ __align__(16) float g_Bpad[(size_t)NB * NC * BPAD_H * BPAD_W];
__device__ __align__(16) float g_raw [(size_t)NB * ND2 * HR * WRP];

#define NA_ELE ((long)NB * 20 * NC * 8 * APAD_W)
#define NBP_ELE ((long)NB * NC * BPAD_H * BPAD_W)

// ---------------- Pass 0: pad/reshape both inputs (one kernel) ----------------
__global__ void pad_AB(const float* __restrict__ in1, const float* __restrict__ in2) {
    long idx = (long)blockIdx.x * blockDim.x + threadIdx.x;
    if (idx < NA_ELE) {
        int col = (int)(idx % APAD_W);
        long rest = idx / APAD_W;
        int rr = (int)(rest % 8);
        rest /= 8;
        int c = (int)(rest % NC);
        rest /= NC;
        int yt = (int)(rest % 20);
        int b  = (int)(rest / 20);
        g_Apad[idx] = in1[(((long)b * NC + c) * NH + yt * 8 + rr + 17) * NW + (col + 17)];
    } else {
        long j = idx - NA_ELE;
        if (j >= NBP_ELE) return;
        int xx = (int)(j % BPAD_W);
        long rest = j / BPAD_W;
        int yy = (int)(rest % BPAD_H);
        long bc = rest / BPAD_H;
        int sy = yy - 3, sx = xx - 3;
        float v = 0.f;
        if ((unsigned)sy < NH && (unsigned)sx < NW)
            v = in2[(bc * NH + sy) * NW + sx];
        g_Bpad[j] = v;
    }
}

// ---------------- TMA / mbarrier helpers ----------------
__device__ __forceinline__ void bulk_cp(uint32_t dst, const void* src,
                                        uint32_t bytes, uint32_t mbar) {
    asm volatile(
        "cp.async.bulk.shared::cta.global.mbarrier::complete_tx::bytes [%0], [%1], %2, [%3];"
        :: "r"(dst), "l"(src), "r"(bytes), "r"(mbar) : "memory");
}

__device__ __forceinline__ void mbar_wait(uint32_t mbar, uint32_t parity) {
    asm volatile(
        "{\n\t.reg .pred P;\n\t"
        "W_%=:\n\t"
        "mbarrier.try_wait.parity.acquire.cta.shared::cta.b64 P, [%0], %1, 10000000;\n\t"
        "@P bra D_%=;\n\t"
        "bra W_%=;\n\t"
        "D_%=:\n\t}"
        :: "r"(mbar), "r"(parity) : "memory");
}

__device__ __forceinline__ void mbar_arrive(uint32_t mbar) {
    asm volatile("mbarrier.arrive.shared.b64 _, [%0];" :: "r"(mbar) : "memory");
}

__device__ __forceinline__ void fill_stage(uint32_t sbase, int i,
                                           int b, int yt, int d) {
    const int s = i & 3;
    const uint32_t mbar = sbase + s * 8;
    const int c0 = i * 4;
    asm volatile("mbarrier.arrive.expect_tx.shared.b64 _, [%0], %1;"
                 :: "r"(mbar), "r"((uint32_t)STAGE_TX) : "memory");
    const char* srcA = (const char*)g_Apad +
        (((long)b * 20 + yt) * NC + c0) * (long)(8 * APAD_W * 4);
    bulk_cp(sbase + A_OFF + s * A_STAGE, srcA, A_STAGE, mbar);
    #pragma unroll
    for (int cc = 0; cc < 4; ++cc) {
        const char* srcB = (const char*)g_Bpad +
            (((long)b * NC + c0 + cc) * BPAD_H + yt * 8 + 20 + d) * (long)(BPAD_W * 4);
        bulk_cp(sbase + B_OFF + s * B_STAGE + cc * B_CC, srcB, B_CC, mbar);
    }
}

// packed fp32x2 FMA
#define FMA2(acc, av, bv) \
    asm("fma.rn.f32x2 %0, %1, %2, %0;" : "+l"(acc) : "l"(av), "l"(bv))

__device__ __forceinline__ void load_ops(const char* abase, const char* bbase, int cc,
                                         unsigned long long* a2, unsigned long long* b2) {
    const ulonglong2* aq = (const ulonglong2*)(abase + cc * A_CC);
    const ulonglong2* bq = (const ulonglong2*)(bbase + cc * B_CC);
    ulonglong2 v0 = aq[0], v1 = aq[1];
    a2[0] = v0.x; a2[1] = v0.y; a2[2] = v1.x; a2[3] = v1.y;
    #pragma unroll
    for (int m = 0; m < 7; ++m) {
        ulonglong2 v = bq[m];
        b2[2*m] = v.x; b2[2*m+1] = v.y;
    }
}

// Main stage loop; PROD instance also produces (tid 0 fills).
template<bool PROD, int JN, int OFF2>
__device__ __forceinline__ void run_team(char* smc, uint32_t sbase, int tid,
                                         int r, int x0, int bcol,
                                         unsigned long long* acc2,
                                         int b, int yt, int d) {
    for (int i = 0; i < 32; ++i) {
        const int s = i & 3;
        const int k = (i >> 2) & 1;
        mbar_wait(sbase + s * 8, k);

        const char* abase = smc + A_OFF + s * A_STAGE + r * A_ROW + x0 * 4;
        const char* bbase = smc + B_OFF + s * B_STAGE + r * B_ROW + bcol + x0 * 4;

        unsigned long long a2[2][4], b2[2][14];
        load_ops(abase, bbase, 0, a2[0], b2[0]);
        #pragma unroll
        for (int cc = 0; cc < 4; ++cc) {
            const int cur = cc & 1;
            if (cc < 3)
                load_ops(abase, bbase, cc + 1, a2[cur ^ 1], b2[cur ^ 1]);
            #pragma unroll
            for (int j = 0; j < JN; ++j)
                #pragma unroll
                for (int p = 0; p < 4; ++p)
                    FMA2(acc2[j * 4 + p], a2[cur][p], b2[cur][j + p + OFF2]);
        }

        __syncwarp();
        if ((tid & 31) == 0)
            mbar_arrive(sbase + 32 + s * 8);
        if (PROD) {
            if (tid == 0 && i + NSTAGE < 32) {
                mbar_wait(sbase + 32 + s * 8, k);
                fill_stage(sbase, i + NSTAGE, b, yt, d);
            }
        }
    }
}

// ---------------- Pass 1: raw correlation ----------------
// grid (dyi, yt, b); block 320 = 2 teams x (8 rows x 20 x-groups).
// team0: dxi 0..10 ; team1: dxi 11..20 (no duplicate work).
extern __shared__ char smem_dyn[];

__global__ __launch_bounds__(320)
void corr_pass1() {
    const int dyi = blockIdx.x;
    const int yt  = blockIdx.y;
    const int b   = blockIdx.z;
    const int d   = 2 * dyi - 20;

    const int tid  = threadIdx.x;
    const int team = (tid >= 160);
    const int t    = tid - team * 160;
    const int r    = t & 7;
    const int g    = t >> 3;
    const int x0   = g * 8;
    const int y    = yt * 8 + r;

    char* smc = smem_dyn;
    const uint32_t sbase = (uint32_t)__cvta_generic_to_shared(smc);

    if (tid == 0) {
        #pragma unroll
        for (int s = 0; s < NSTAGE; ++s) {
            asm volatile("mbarrier.init.shared.b64 [%0], 1;"
                         :: "r"(sbase + s * 8) : "memory");           // full
            asm volatile("mbarrier.init.shared.b64 [%0], 10;"
                         :: "r"(sbase + 32 + s * 8) : "memory");      // empty (10 warps)
        }
        asm volatile("fence.proxy.async.shared::cta;" ::: "memory");
    }
    __syncthreads();

    if (tid == 0) {
        fill_stage(sbase, 0, b, yt, d);
        fill_stage(sbase, 1, b, yt, d);
        fill_stage(sbase, 2, b, yt, d);
        fill_stage(sbase, 3, b, yt, d);
    }

    unsigned long long acc2[44];
    #pragma unroll
    for (int p = 0; p < 44; ++p) acc2[p] = 0ull;

    if (team == 0)
        run_team<true, 11, 0>(smc, sbase, tid, r, x0, 0, acc2, b, yt, d);
    else
        run_team<false, 10, 1>(smc, sbase, tid, r, x0, 80, acc2, b, yt, d);

    if (y < HR) {
        const int jn = team ? 10 : 11;
        const int chbase = dyi * ND + team * 11;
        for (int j = 0; j < jn; ++j) {
            int ch = chbase + j;
            size_t base = (((size_t)b * ND2 + ch) * HR + y) * WRP + x0;
            ulonglong2 o0, o1;
            o0.x = acc2[j*4+0]; o0.y = acc2[j*4+1];
            o1.x = acc2[j*4+2]; o1.y = acc2[j*4+3];
            *reinterpret_cast<ulonglong2*>(&g_raw[base])     = o0;
            *reinterpret_cast<ulonglong2*>(&g_raw[base + 4]) = o1;
        }
    }
}

// ---------------- Pass 2: 3x3 box sum / 1152, 4x4 patch per thread ----------------
__global__ void corr_pass2(float* __restrict__ out) {
    const int tid = threadIdx.x;            // 156
    const int qx = tid % 39;
    const int qy = blockIdx.y * 4 + tid / 39;
    const int ch = blockIdx.z;
    if (qy >= 39) return;
    const int i0 = qy * 4, j0 = qx * 4;
    const float inv = 1.0f / 1152.0f;

    const float* rawb = g_raw + (size_t)ch * HR * WRP;
    float w[6][4];
    #pragma unroll
    for (int rr = 0; rr < 6; ++rr) {
        const float4* p = (const float4*)(rawb + (size_t)(i0 + rr) * WRP + j0);
        float4 u = p[0], v = p[1];
        w[rr][0] = u.x + u.y + u.z;
        w[rr][1] = u.y + u.z + u.w;
        w[rr][2] = u.z + u.w + v.x;
        w[rr][3] = u.w + v.x + v.y;
    }
    float* ob = out + (size_t)ch * HO * WO + j0;
    #pragma unroll
    for (int i = 0; i < 4; ++i) {
        float4 o;
        o.x = (w[i][0] + w[i+1][0] + w[i+2][0]) * inv;
        o.y = (w[i][1] + w[i+1][1] + w[i+2][1]) * inv;
        o.z = (w[i][2] + w[i+1][2] + w[i+2][2]) * inv;
        o.w = (w[i][3] + w[i+1][3] + w[i+2][3]) * inv;
        *reinterpret_cast<float4*>(ob + (size_t)(i0 + i) * WO) = o;
    }
}

extern "C" void kernel_launch(void* const* d_in, const int* in_sizes, int n_in,
                              void* d_out, int out_size) {
    const float* in1 = (const float*)d_in[0];
    const float* in2 = (const float*)d_in[1];
    float* out = (float*)d_out;

    long ntot = NA_ELE + NBP_ELE;
    pad_AB<<<(unsigned)((ntot + 255) / 256), 256>>>(in1, in2);

    cudaFuncSetAttribute(corr_pass1,
                         cudaFuncAttributeMaxDynamicSharedMemorySize, SMEM_BYTES);

    dim3 g1(21, 20, 4), b1(320);
    corr_pass1<<<g1, b1, SMEM_BYTES>>>();

    dim3 g2(1, 10, NB * ND2), b2(156);
    corr_pass2<<<g2, b2>>>(out);
}

// round 9
// speedup vs baseline: 1.4409x; 1.4409x over previous
#include <cuda_runtime.h>
#include <cstdint>

#define HR 158
#define HO 156
#define WO 156
#define CH_STRIDE (158*160)

// smem map (bytes)
#define SA_STR 528                 // 132 floats per row
#define SM_A   0
#define A_BYTES (80*SA_STR)        // 42240
#define SM_B0  A_BYTES
#define B_BYTES (104*SA_STR)       // 54912
#define SM_B1  (SM_B0 + B_BYTES)
#define SM_DS  (SM_B1 + B_BYTES)   // 152064
#define SMEM_TOTAL (SM_DS + 21*80*4)   // 158784

// At: [b][y 158][p 2][m 80][c 128]   (~52 MB)
__device__ __align__(16) float g_At[(size_t)4*158*2*80*128];
// Bt: [b][y2i 198][p 2][n 104][c 128] (~84 MB)
__device__ __align__(16) float g_Bt[(size_t)4*198*2*104*128];
// raw, parity-split rows: [b*441+ch][y 158][p 2][m 80]  (~178 MB)
__device__ __align__(16) float g_raw[(size_t)4*441*158*160];

static __device__ __forceinline__ float to_tf32(float x){
    float r; asm("cvt.rna.tf32.f32 %0, %1;" : "=f"(r) : "f"(x)); return r;
}

// ---------------- Pass 0: transpose/pad to K-major tf32 tiles ----------------
// At[m][c] = tf32(in1[c, y+17, 2m+p+17]), m<=78 else 0
__global__ __launch_bounds__(256) void transA(const float* __restrict__ in1){
    __shared__ float sm[32*193];
    const int y = blockIdx.x, b = blockIdx.y;
    const int tid = threadIdx.x, w = tid >> 5, lane = tid & 31;
    float* outb = g_At + (size_t)((b*158 + y)*2) * (80*128);
    for (int c0 = 0; c0 < 128; c0 += 32){
        __syncthreads();
        for (int idx = tid; idx < 32*192; idx += 256){
            int cl = idx / 192, xx = idx - cl*192;
            sm[cl*193 + xx] = in1[(((size_t)b*128 + c0 + cl)*192 + (y+17))*192 + xx];
        }
        __syncthreads();
        #pragma unroll
        for (int it = 0; it < 20; ++it){
            int combo = w + (it << 3);          // 0..159
            int pp = combo / 80, m = combo - pp*80;
            int xs = 2*m + pp + 17;
            float v = (m <= 78) ? sm[lane*193 + xs] : 0.f;
            outb[((size_t)pp*80 + m)*128 + c0 + lane] = to_tf32(v);
        }
    }
}

// Bt[n][c] = tf32(in2[c, y2i-3, 2n+p-3]), 0 if OOB
__global__ __launch_bounds__(256) void transB(const float* __restrict__ in2){
    __shared__ float sm[32*193];
    const int y2i = blockIdx.x, b = blockIdx.y;
    const int y2 = y2i - 3;
    const bool rowok = (y2 >= 0 && y2 < 192);
    const int tid = threadIdx.x, w = tid >> 5, lane = tid & 31;
    float* outb = g_Bt + (size_t)((b*198 + y2i)*2) * (104*128);
    for (int c0 = 0; c0 < 128; c0 += 32){
        __syncthreads();
        for (int idx = tid; idx < 32*192; idx += 256){
            int cl = idx / 192, xx = idx - cl*192;
            sm[cl*193 + xx] = rowok ?
                in2[(((size_t)b*128 + c0 + cl)*192 + y2)*192 + xx] : 0.f;
        }
        __syncthreads();
        #pragma unroll
        for (int it = 0; it < 26; ++it){
            int combo = w + (it << 3);          // 0..207
            if (combo < 208){
                int pp = combo / 104, n = combo - pp*104;
                int xs = 2*n + pp - 3;
                float v = (xs >= 0 && xs < 192) ? sm[lane*193 + xs] : 0.f;
                outb[((size_t)pp*104 + n)*128 + c0 + lane] = to_tf32(v);
            }
        }
    }
}

// ---------------- helpers ----------------
__device__ __forceinline__ void cpa16(uint32_t dst, const void* src){
    asm volatile("cp.async.cg.shared.global [%0], [%1], 16;" :: "r"(dst), "l"(src));
}
__device__ __forceinline__ void mma8(float* d, const uint32_t* a, uint32_t b0, uint32_t b1){
    asm volatile(
        "mma.sync.aligned.m16n8k8.row.col.f32.tf32.tf32.f32 "
        "{%0,%1,%2,%3}, {%4,%5,%6,%7}, {%8,%9}, {%0,%1,%2,%3};"
        : "+f"(d[0]), "+f"(d[1]), "+f"(d[2]), "+f"(d[3])
        : "r"(a[0]), "r"(a[1]), "r"(a[2]), "r"(a[3]), "r"(b0), "r"(b1));
}

// ---------------- Pass 1: banded tf32 MMA ----------------
// grid (y 158, p 2, b 4); block 160 = 5 warps, warp w owns m-rows 16w..16w+15.
// For pane i (=dyi): D[m,n] = sum_c At[m,c]*Bt(y+2i)[n,c]; raw[dxi = n-m].
extern __shared__ __align__(16) char smem_dyn[];

__global__ __launch_bounds__(160)
void corr_mma(){
    const int y = blockIdx.x, p = blockIdx.y, b = blockIdx.z;
    const int tid = threadIdx.x, w = tid >> 5, lane = tid & 31;
    const int grp = lane >> 2, tig = lane & 3;
    char* smc = smem_dyn;
    const uint32_t sb = (uint32_t)__cvta_generic_to_shared(smc);
    float* Dsm = (float*)(smc + SM_DS);

    // fill A + B0, commit as group 0
    {
        const float* Ab = g_At + ((size_t)(b*158 + y)*2 + p) * (80*128);
        for (int idx = tid; idx < 2560; idx += 160){
            int m = idx >> 5, j = idx & 31;
            cpa16(sb + SM_A + m*SA_STR + j*16, Ab + m*128 + j*4);
        }
        const float* Bb = g_Bt + ((size_t)(b*198 + y)*2 + p) * (104*128);
        for (int idx = tid; idx < 3328; idx += 160){
            int n = idx >> 5, j = idx & 31;
            cpa16(sb + SM_B0 + n*SA_STR + j*16, Bb + n*128 + j*4);
        }
        asm volatile("cp.async.commit_group;" ::: "memory");
    }

    const uint32_t* smA = (const uint32_t*)(smc + SM_A + (16*w + grp)*SA_STR + tig*4);
    const int m0 = 16*w + grp;

    for (int pane = 0; pane <= 20; ++pane){
        const int s = pane & 1;
        if (pane < 20){
            const float* Bn = g_Bt +
                ((size_t)(b*198 + y + 2*(pane+1))*2 + p) * (104*128);
            const uint32_t dstb = sb + (((pane+1) & 1) ? SM_B1 : SM_B0);
            for (int idx = tid; idx < 3328; idx += 160){
                int n = idx >> 5, j = idx & 31;
                cpa16(dstb + n*SA_STR + j*16, Bn + n*128 + j*4);
            }
            asm volatile("cp.async.commit_group;" ::: "memory");
            asm volatile("cp.async.wait_group 1;" ::: "memory");
        } else {
            asm volatile("cp.async.wait_group 0;" ::: "memory");
        }
        __syncthreads();

        const uint32_t* smB = (const uint32_t*)(smc + (s ? SM_B1 : SM_B0) +
                                                (16*w + grp)*SA_STR + tig*4);
        float d[5][4];
        #pragma unroll
        for (int t = 0; t < 5; ++t)
            #pragma unroll
            for (int q = 0; q < 4; ++q) d[t][q] = 0.f;

        #pragma unroll
        for (int ks = 0; ks < 16; ++ks){
            uint32_t a[4];
            a[0] = smA[ks*8];
            a[1] = smA[ks*8 + 8*132];
            a[2] = smA[ks*8 + 4];
            a[3] = smA[ks*8 + 8*132 + 4];
            #pragma unroll
            for (int t = 0; t < 5; ++t){
                uint32_t b0 = smB[t*8*132 + ks*8];
                uint32_t b1 = smB[t*8*132 + ks*8 + 4];
                mma8(d[t], a, b0, b1);
            }
        }

        // band extraction: Dsm[dxi][m]
        #pragma unroll
        for (int t = 0; t < 5; ++t){
            int n0 = 16*w + 8*t + 2*tig;
            int dx0 = n0 - m0;
            if ((unsigned)dx0 < 21u)       Dsm[dx0*80 + m0]       = d[t][0];
            if ((unsigned)(dx0+1) < 21u)   Dsm[(dx0+1)*80 + m0]   = d[t][1];
            if (m0 + 8 <= 78){
                int dx2 = dx0 - 8;
                if ((unsigned)dx2 < 21u)     Dsm[dx2*80 + m0+8]     = d[t][2];
                if ((unsigned)(dx2+1) < 21u) Dsm[(dx2+1)*80 + m0+8] = d[t][3];
            }
        }
        __syncthreads();

        // coalesced store of 21 x 80 band rows
        {
            const int mloc = (tid >= 80) ? tid - 80 : tid;
            const int dxi0 = (tid >= 80) ? 1 : 0;
            float* orow = g_raw + ((size_t)(b*441 + pane*21) * 158 + y) * 160
                          + p*80 + mloc;
            #pragma unroll
            for (int k = 0; k < 10; ++k){
                int dxi = 2*k + dxi0;
                orow[(size_t)dxi * CH_STRIDE] = Dsm[dxi*80 + mloc];
            }
            if (dxi0 == 0)
                orow[(size_t)20 * CH_STRIDE] = Dsm[20*80 + mloc];
        }
    }
}

// ---------------- Pass 2: 3x3 box sum / 1152 on parity-split rows ----------------
__global__ void corr_pass2(float* __restrict__ out){
    const int tid = threadIdx.x;            // 156
    const int qx = tid % 39;
    const int qy = blockIdx.y * 4 + tid / 39;
    const int ch = blockIdx.z;
    if (qy >= 39) return;
    const int i0 = qy * 4, j0 = qx * 4, m0 = qx * 2;
    const float inv = 1.0f / 1152.0f;

    const float* rb = g_raw + (size_t)ch * CH_STRIDE;
    float w6[6][4];
    #pragma unroll
    for (int rr = 0; rr < 6; ++rr){
        const float* row = rb + (size_t)(i0 + rr) * 160;
        float2 u = *(const float2*)(row + m0);        // p0[m0], p0[m0+1]
        float  u2 = row[m0 + 2];                      // p0[m0+2]
        float2 v = *(const float2*)(row + 80 + m0);   // p1[m0], p1[m0+1]
        float  v2 = row[80 + m0 + 2];                 // p1[m0+2]
        w6[rr][0] = u.x + v.x + u.y;
        w6[rr][1] = v.x + u.y + v.y;
        w6[rr][2] = u.y + v.y + u2;
        w6[rr][3] = v.y + u2 + v2;
    }
    float* ob = out + (size_t)ch * HO * WO + j0;
    #pragma unroll
    for (int i = 0; i < 4; ++i){
        float4 o;
        o.x = (w6[i][0] + w6[i+1][0] + w6[i+2][0]) * inv;
        o.y = (w6[i][1] + w6[i+1][1] + w6[i+2][1]) * inv;
        o.z = (w6[i][2] + w6[i+1][2] + w6[i+2][2]) * inv;
        o.w = (w6[i][3] + w6[i+1][3] + w6[i+2][3]) * inv;
        *reinterpret_cast<float4*>(ob + (size_t)(i0 + i) * WO) = o;
    }
}

extern "C" void kernel_launch(void* const* d_in, const int* in_sizes, int n_in,
                              void* d_out, int out_size){
    const float* in1 = (const float*)d_in[0];
    const float* in2 = (const float*)d_in[1];
    float* out = (float*)d_out;

    transA<<<dim3(158, 4), 256>>>(in1);
    transB<<<dim3(198, 4), 256>>>(in2);

    cudaFuncSetAttribute(corr_mma,
                         cudaFuncAttributeMaxDynamicSharedMemorySize, SMEM_TOTAL);
    corr_mma<<<dim3(158, 2, 4), 160, SMEM_TOTAL>>>();

    dim3 g2(1, 10, 4*441), b2(156);
    corr_pass2<<<g2, b2>>>(out);
}